// round 14
// baseline (speedup 1.0000x reference)
#include <cuda_runtime.h>
#include <cuda_fp16.h>
#include <math.h>
#include <stdint.h>

#define DD 512
#define NN 128
#define BB 2
#define MBIG (BB*NN*NN)     // 32768 rows for big GEMMs
#define XROWS (BB*NN)       // 256 rows for small GEMMs

// ---------------- scratch (static device allocations; no cudaMalloc) ----------------
__device__ __half g_AH[MBIG*DD];            // rel plane A (fp16)
__device__ __half g_BH[MBIG*DD];            // rel plane B (fp16)
__device__ __half g_WgH[DD*DD];             // Wg3^T  fp16 [n][k]
__device__ __half g_WeH[DD*DD];             // Wesa^T fp16 [n][k]
__device__ __half g_WraT[DD*DD], g_WrbT[DD*DD];
__device__ __half g_Wg1T[DD*DD], g_Wg2T[DD*DD], g_WgoT[DD*DD];
__device__ __half g_X0H[XROWS*DD];
__device__ __half g_UH [XROWS*DD];
__device__ __half g_VH [XROWS*DD];
__device__ __half g_X1H[XROWS*DD];
__device__ __half g_X2H[XROWS*DD];
__device__ float g_s [XROWS*DD];
__device__ float g_t [XROWS*DD];
__device__ float g_p [XROWS*DD];
__device__ float g_q [XROWS*DD];
__device__ float g_c [DD];
__device__ float g_mx [XROWS*DD];
__device__ float g_inv[XROWS*DD];

// ---------------- helpers ----------------
__device__ __forceinline__ uint32_t smem_u32(const void* p) {
    uint32_t a;
    asm("{ .reg .u64 t; cvta.to.shared.u64 t, %1; cvt.u32.u64 %0, t; }" : "=r"(a) : "l"(p));
    return a;
}
__device__ __forceinline__ void mma16816(float* c, const uint32_t* a, const uint32_t* b) {
    asm volatile(
        "mma.sync.aligned.m16n8k16.row.col.f32.f16.f16.f32 "
        "{%0,%1,%2,%3},{%4,%5,%6,%7},{%8,%9},{%0,%1,%2,%3};"
        : "+f"(c[0]), "+f"(c[1]), "+f"(c[2]), "+f"(c[3])
        : "r"(a[0]), "r"(a[1]), "r"(a[2]), "r"(a[3]), "r"(b[0]), "r"(b[1]));
}
#define LDSM4(r0,r1,r2,r3,addr) \
    asm volatile("ldmatrix.sync.aligned.m8n8.x4.shared.b16 {%0,%1,%2,%3}, [%4];" \
        : "=r"(r0),"=r"(r1),"=r"(r2),"=r"(r3) : "r"(addr))
__device__ __forceinline__ void cp16(uint32_t dst, const void* src) {
    asm volatile("cp.async.cg.shared.global [%0], [%1], 16;" :: "r"(dst), "l"(src) : "memory");
}
// fast tanh: abs err ~1e-7, saturates correctly at +/-inf
__device__ __forceinline__ float ftanh(float x) {
    float e = __expf(2.0f * x);
    return 1.0f - __fdividef(2.0f, e + 1.0f);
}

// ---------------- weight transpose+f16: 7 weights in one launch ----------------
struct TransBatch { const float* src[7]; __half* dst[7]; };
__global__ void transsplit_kernel(TransBatch tb) {
    const float* W  = tb.src[blockIdx.z];
    __half*      Wh = tb.dst[blockIdx.z];
    __shared__ float tile[32][33];
    int x = blockIdx.x * 32 + threadIdx.x;
    int y = blockIdx.y * 32 + threadIdx.y;
    #pragma unroll
    for (int r = 0; r < 32; r += 8) tile[threadIdx.y + r][threadIdx.x] = W[(y + r) * DD + x];
    __syncthreads();
    x = blockIdx.y * 32 + threadIdx.x;   // now k index
    y = blockIdx.x * 32 + threadIdx.y;   // now n index
    #pragma unroll
    for (int r = 0; r < 32; r += 8)
        Wh[(y + r) * DD + x] = __float2half_rn(tile[threadIdx.x][threadIdx.y + r]);
}

// ---------------- x0 -> fp16 ----------------
__global__ void tohalf_kernel(const float* __restrict__ src, __half* __restrict__ dst) {
    int i = (blockIdx.x * 256 + threadIdx.x) * 2;
    float2 v = *(const float2*)(src + i);
    *(__half2*)(dst + i) = __halves2half2(__float2half_rn(v.x), __float2half_rn(v.y));
}

// ---------------- c = b_rel @ Wg3 + b_gr ----------------
__global__ void cvec_kernel(const float* __restrict__ b_rel,
                            const float* __restrict__ Wg3,
                            const float* __restrict__ b_gr,
                            float* __restrict__ c) {
    int d = threadIdx.x;
    float acc = b_gr[d];
    #pragma unroll 8
    for (int k = 0; k < DD; ++k)
        acc += b_rel[k] * Wg3[k*DD + d];
    c[d] = acc;
}

// ---------------- rel1 init: f16(tanh(s_i + t_j + c)) ----------------
__global__ __launch_bounds__(256)
void init_rel_kernel(const float* __restrict__ s, const float* __restrict__ t,
                     const float* __restrict__ c, __half* __restrict__ RH) {
    __shared__ float srow[DD];
    int bi = blockIdx.x;                 // b*128 + i
    int b  = bi >> 7;
    int tid = threadIdx.x;
    #pragma unroll
    for (int d = tid; d < DD; d += 256) srow[d] = s[bi * DD + d] + c[d];
    __syncthreads();
    int j0 = blockIdx.y * 32;
    int d = tid * 2;
    for (int j = j0; j < j0 + 32; ++j) {
        const float* trow = t + (size_t)((b << 7) + j) * DD;
        float v0 = ftanh(srow[d]   + trow[d]);
        float v1 = ftanh(srow[d+1] + trow[d+1]);
        size_t m = (size_t)bi * NN + j;
        *(__half2*)&RH[m * DD + d] = __halves2half2(__float2half_rn(v0), __float2half_rn(v1));
    }
}

#define HG_SMEM (3*20480)
#define HS_SMEM (5*20480)

// ---------------- small batched tensor GEMM (5-stage ring): C = act?(A@Wt [+bias] [+Cadd]) ----------------
struct HJob {
    const __half* A; const __half* W; const float* bias; const float* Cadd;
    float* Cf; __half* Ch; int act; int pad;
};
struct HBatch { HJob jobs[5]; };

__global__ __launch_bounds__(256, 1)
void hsmall_kernel(HBatch batch) {
    HJob jb = batch.jobs[blockIdx.z];
    extern __shared__ __align__(16) char sm[];
    const uint32_t smBase = smem_u32(sm);
    const int tid = threadIdx.x;
    const int n0 = blockIdx.x << 7, m0 = blockIdx.y << 7;

    const int mat = tid >> 7, tt = tid & 127;
    const __half* plane = mat ? (jb.W + (size_t)(n0 + tt) * DD) : (jb.A + (size_t)(m0 + tt) * DD);
    const uint32_t dstoff = (uint32_t)mat * 10240u + (uint32_t)tt * 80u;

    const int lane = tid & 31, wid = tid >> 5;
    const int g = lane >> 2, q = lane & 3;
    const int wm = (wid & 1) * 64, wn = (wid >> 1) * 32;
    const int lr = lane & 7, sub = lane >> 3;
    const uint32_t rowsel = (uint32_t)((sub & 1) * 8 + lr);
    const uint32_t colsel = (uint32_t)((sub >> 1) * 16);
    const uint32_t aoff = (uint32_t)(wm + rowsel) * 80u + colsel;
    const uint32_t boff = 10240u + (uint32_t)(wn + rowsel) * 80u + colsel;

    float cacc[4][4][4];
    #pragma unroll
    for (int a = 0; a < 4; ++a)
        #pragma unroll
        for (int b = 0; b < 4; ++b)
            #pragma unroll
            for (int e = 0; e < 4; ++e) cacc[a][b][e] = 0.f;

    // prologue: chunks 0..3 -> stages 0..3
    #pragma unroll
    for (int c0 = 0; c0 < 4; ++c0) {
        uint32_t d = smBase + (uint32_t)c0 * 20480u + dstoff;
        const __half* sp = plane + c0 * 32;
        #pragma unroll
        for (int sg = 0; sg < 4; ++sg) cp16(d + sg*16, sp + sg*8);
        asm volatile("cp.async.commit_group;" ::: "memory");
    }

    int stComp = 0;
    for (int kc = 0; kc < 16; ++kc) {
        asm volatile("cp.async.wait_group 3;" ::: "memory");   // chunk kc certified (empty tail groups keep the count uniform)
        __syncthreads();

        if (kc + 4 < 16) {
            int stLoad = stComp - 1; if (stLoad < 0) stLoad = 4;   // stage freed by chunk kc-1
            uint32_t d = smBase + (uint32_t)stLoad * 20480u + dstoff;
            const __half* sp = plane + (kc + 4) * 32;
            #pragma unroll
            for (int sg = 0; sg < 4; ++sg) cp16(d + sg*16, sp + sg*8);
        }
        asm volatile("cp.async.commit_group;" ::: "memory");   // possibly empty group (tail)

        uint32_t bufb = smBase + (uint32_t)stComp * 20480u;
        #pragma unroll
        for (int ks = 0; ks < 2; ++ks) {
            uint32_t kso = (uint32_t)(ks * 32);
            uint32_t bfh[4][2];
            #pragma unroll
            for (int ntp = 0; ntp < 2; ++ntp) {
                uint32_t ba = bufb + boff + (uint32_t)ntp * 1280u + kso;
                uint32_t r0, r1, r2, r3;
                LDSM4(r0, r1, r2, r3, ba);
                bfh[2*ntp][0]=r0; bfh[2*ntp+1][0]=r1; bfh[2*ntp][1]=r2; bfh[2*ntp+1][1]=r3;
            }
            #pragma unroll
            for (int mt = 0; mt < 4; ++mt) {
                uint32_t aa = bufb + aoff + (uint32_t)mt * 1280u + kso;
                uint32_t ah[4];
                LDSM4(ah[0], ah[1], ah[2], ah[3], aa);
                #pragma unroll
                for (int nt = 0; nt < 4; ++nt)
                    mma16816(cacc[mt][nt], ah, bfh[nt]);
            }
        }
        if (++stComp == 5) stComp = 0;
    }

    // ---- epilogue ----
    #pragma unroll
    for (int mt = 0; mt < 4; ++mt) {
        #pragma unroll
        for (int nt = 0; nt < 4; ++nt) {
            int col = n0 + wn + nt*8 + q*2;
            float b0 = 0.f, b1 = 0.f;
            if (jb.bias) { b0 = jb.bias[col]; b1 = jb.bias[col + 1]; }
            #pragma unroll
            for (int rh = 0; rh < 2; ++rh) {
                int r = m0 + wm + mt*16 + g + rh*8;
                float v0 = cacc[mt][nt][rh*2 + 0] + b0;
                float v1 = cacc[mt][nt][rh*2 + 1] + b1;
                if (jb.Cadd) {
                    float2 cv = *(const float2*)(jb.Cadd + (size_t)r * DD + col);
                    v0 += cv.x; v1 += cv.y;
                }
                if (jb.act) { v0 = ftanh(v0); v1 = ftanh(v1); }
                if (jb.Cf)
                    *(float2*)(jb.Cf + (size_t)r * DD + col) = make_float2(v0, v1);
                else
                    *(__half2*)(jb.Ch + (size_t)r * DD + col) =
                        __halves2half2(__float2half_rn(v0), __float2half_rn(v1));
            }
        }
    }
}

// ================= big GEMM via mma.sync (fp16, 3-stage cp.async ring) =================
template<int MODE>
__global__ __launch_bounds__(256, 2)
void hgemm_kernel(const __half* __restrict__ Ah, const __half* __restrict__ Bh,
                  const float* __restrict__ P, const float* __restrict__ Q,
                  const float* __restrict__ bias, __half* __restrict__ Chi) {
    extern __shared__ __align__(16) char sm[];
    const uint32_t smBase = smem_u32(sm);
    const int tid = threadIdx.x;
    const int n0 = blockIdx.x << 7, m0 = blockIdx.y << 7;

    const int mat = tid >> 7, tt = tid & 127;
    const __half* plane = mat ? (Bh + (size_t)(n0 + tt) * DD) : (Ah + (size_t)(m0 + tt) * DD);
    const uint32_t dstoff = (uint32_t)mat * 10240u + (uint32_t)tt * 80u;

    const int lane = tid & 31, wid = tid >> 5;
    const int g = lane >> 2, q = lane & 3;
    const int wm = (wid & 1) * 64, wn = (wid >> 1) * 32;
    const int lr = lane & 7, sub = lane >> 3;
    const uint32_t rowsel = (uint32_t)((sub & 1) * 8 + lr);
    const uint32_t colsel = (uint32_t)((sub >> 1) * 16);
    const uint32_t aoff = (uint32_t)(wm + rowsel) * 80u + colsel;
    const uint32_t boff = 10240u + (uint32_t)(wn + rowsel) * 80u + colsel;

    const uint32_t stage0 = smBase, stage1 = smBase + 20480u, stage2 = smBase + 40960u;

    float cacc[4][4][4];
    #pragma unroll
    for (int a = 0; a < 4; ++a)
        #pragma unroll
        for (int b = 0; b < 4; ++b)
            #pragma unroll
            for (int e = 0; e < 4; ++e) cacc[a][b][e] = 0.f;

    {
        uint32_t d = stage0 + dstoff;
        #pragma unroll
        for (int sg = 0; sg < 4; ++sg) cp16(d + sg*16, plane + sg*8);
        asm volatile("cp.async.commit_group;" ::: "memory");
        d = stage1 + dstoff;
        const __half* sp = plane + 32;
        #pragma unroll
        for (int sg = 0; sg < 4; ++sg) cp16(d + sg*16, sp + sg*8);
        asm volatile("cp.async.commit_group;" ::: "memory");
    }

    uint32_t stComp = stage0, stLoad = stage2;
    for (int kc = 0; kc < 16; ++kc) {
        if (kc < 15) asm volatile("cp.async.wait_group 1;" ::: "memory");
        else         asm volatile("cp.async.wait_group 0;" ::: "memory");
        __syncthreads();

        if (kc + 2 < 16) {
            uint32_t d = stLoad + dstoff;
            const __half* sp = plane + (kc + 2) * 32;
            #pragma unroll
            for (int sg = 0; sg < 4; ++sg) cp16(d + sg*16, sp + sg*8);
            asm volatile("cp.async.commit_group;" ::: "memory");
        }

        uint32_t bufb = stComp;
        #pragma unroll
        for (int ks = 0; ks < 2; ++ks) {
            uint32_t kso = (uint32_t)(ks * 32);
            uint32_t bfh[4][2];
            #pragma unroll
            for (int ntp = 0; ntp < 2; ++ntp) {
                uint32_t ba = bufb + boff + (uint32_t)ntp * 1280u + kso;
                uint32_t r0, r1, r2, r3;
                LDSM4(r0, r1, r2, r3, ba);
                bfh[2*ntp][0]=r0; bfh[2*ntp+1][0]=r1; bfh[2*ntp][1]=r2; bfh[2*ntp+1][1]=r3;
            }
            #pragma unroll
            for (int mt = 0; mt < 4; ++mt) {
                uint32_t aa = bufb + aoff + (uint32_t)mt * 1280u + kso;
                uint32_t ah[4];
                LDSM4(ah[0], ah[1], ah[2], ah[3], aa);
                #pragma unroll
                for (int nt = 0; nt < 4; ++nt)
                    mma16816(cacc[mt][nt], ah, bfh[nt]);
            }
        }
        uint32_t newComp = (stComp == stage2) ? stage0 : stComp + 20480u;
        stLoad = stComp;
        stComp = newComp;
    }

    // ---- epilogue ----
    #pragma unroll
    for (int mt = 0; mt < 4; ++mt) {
        #pragma unroll
        for (int nt = 0; nt < 4; ++nt) {
            int col = n0 + wn + nt*8 + q*2;
            float b0 = bias[col], b1 = bias[col + 1];
            #pragma unroll
            for (int rh = 0; rh < 2; ++rh) {
                int r = m0 + wm + mt*16 + g + rh*8;
                float v0 = cacc[mt][nt][rh*2 + 0] + b0;
                float v1 = cacc[mt][nt][rh*2 + 1] + b1;
                if (MODE == 0) {
                    int b = r >> 14, ii = (r >> 7) & 127, jj = r & 127;
                    const float* pr = P + (size_t)(((b<<7)+ii)) * DD;
                    const float* qr = Q + (size_t)(((b<<7)+jj)) * DD;
                    v0 = ftanh(v0 + pr[col]   + qr[col]);
                    v1 = ftanh(v1 + pr[col+1] + qr[col+1]);
                }
                *(__half2*)&Chi[(size_t)r * DD + col] =
                    __halves2half2(__float2half_rn(v0), __float2half_rn(v1));
            }
        }
    }
}

// ---------------- softmax pass A (half2 vectorized) ----------------
__global__ __launch_bounds__(256)
void softmax_stats_kernel(const __half2* __restrict__ rel2,
                          float* __restrict__ mx, float* __restrict__ inv) {
    int bj = blockIdx.x;            // b*NN + j
    int b = bj >> 7, j = bj & 127;
    int d2 = threadIdx.x;           // 0..255 -> d = 2*d2
    const __half2* ptr = rel2 + ((size_t)((b << 14) + j) * DD >> 1) + d2;
    const int strd = NN * DD / 2;
    float2 m = make_float2(-1e30f, -1e30f);
    #pragma unroll 8
    for (int i = 0; i < NN; ++i) {
        float2 v = __half22float2(ptr[(size_t)i * strd]);
        m.x = fmaxf(m.x, v.x); m.y = fmaxf(m.y, v.y);
    }
    float2 s = make_float2(0.f, 0.f);
    #pragma unroll 8
    for (int i = 0; i < NN; ++i) {
        float2 v = __half22float2(ptr[(size_t)i * strd]);
        s.x += __expf(v.x - m.x); s.y += __expf(v.y - m.y);
    }
    int o = bj * DD + d2 * 2;
    *(float2*)(mx + o)  = m;
    *(float2*)(inv + o) = make_float2(1.0f / s.x, 1.0f / s.y);
}

// ---------------- softmax pass B (half2 vectorized) ----------------
__global__ __launch_bounds__(256)
void softmax_out_kernel(const __half2* __restrict__ rel2,
                        const float* __restrict__ mx,
                        const float* __restrict__ inv,
                        float* __restrict__ out) {
    int bi = blockIdx.x;            // b*NN + i
    int b = bi >> 7;
    int d2 = threadIdx.x;
    const __half2* ptr = rel2 + ((size_t)bi * NN * DD >> 1) + d2;
    const float2* mxp = (const float2*)(mx  + (size_t)(b << 7) * DD) + d2;
    const float2* ivp = (const float2*)(inv + (size_t)(b << 7) * DD) + d2;
    const int strd = DD / 2;
    float2 acc = make_float2(0.f, 0.f);
    #pragma unroll 8
    for (int j = 0; j < NN; ++j) {
        float2 v  = __half22float2(ptr[(size_t)j * strd]);
        float2 mm = mxp[j * strd];
        float2 iv = ivp[j * strd];
        acc.x += v.x * __expf(v.x - mm.x) * iv.x;
        acc.y += v.y * __expf(v.y - mm.y) * iv.y;
    }
    *(float2*)(out + (size_t)bi * DD + d2 * 2) = acc;
}

// ---------------- host ----------------
extern "C" void kernel_launch(void* const* d_in, const int* in_sizes, int n_in,
                              void* d_out, int out_size) {
    const float* x0   = (const float*)d_in[0];
    const float* Wrel = (const float*)d_in[1];
    const float* brel = (const float*)d_in[2];
    const float* Wgo  = (const float*)d_in[3];
    const float* bgo  = (const float*)d_in[4];
    const float* Wgr  = (const float*)d_in[5];
    const float* bgr  = (const float*)d_in[6];
    const float* Wesa = (const float*)d_in[7];
    const float* besa = (const float*)d_in[8];
    float* out = (float*)d_out;

    const float* Wra = Wrel;                 // W_rel[0:D]
    const float* Wrb = Wrel + DD*DD;         // W_rel[D:2D]
    const float* Wg1 = Wgr;                  // W_gr[0:D]
    const float* Wg2 = Wgr + DD*DD;          // W_gr[D:2D]
    const float* Wg3 = Wgr + 2*DD*DD;        // W_gr[2D:3D]

    float *bs, *bt, *bp, *bq, *bc, *bmx, *binv;
    __half *AH, *BH, *WgH, *WeH, *WraT, *WrbT, *Wg1T, *Wg2T, *WgoT;
    __half *X0H, *UH, *VH, *X1H, *X2H;
    cudaGetSymbolAddress((void**)&AH, g_AH);
    cudaGetSymbolAddress((void**)&BH, g_BH);
    cudaGetSymbolAddress((void**)&WgH, g_WgH);
    cudaGetSymbolAddress((void**)&WeH, g_WeH);
    cudaGetSymbolAddress((void**)&WraT, g_WraT);
    cudaGetSymbolAddress((void**)&WrbT, g_WrbT);
    cudaGetSymbolAddress((void**)&Wg1T, g_Wg1T);
    cudaGetSymbolAddress((void**)&Wg2T, g_Wg2T);
    cudaGetSymbolAddress((void**)&WgoT, g_WgoT);
    cudaGetSymbolAddress((void**)&X0H, g_X0H);
    cudaGetSymbolAddress((void**)&UH,  g_UH);
    cudaGetSymbolAddress((void**)&VH,  g_VH);
    cudaGetSymbolAddress((void**)&X1H, g_X1H);
    cudaGetSymbolAddress((void**)&X2H, g_X2H);
    cudaGetSymbolAddress((void**)&bs,  g_s);
    cudaGetSymbolAddress((void**)&bt,  g_t);
    cudaGetSymbolAddress((void**)&bp,  g_p);
    cudaGetSymbolAddress((void**)&bq,  g_q);
    cudaGetSymbolAddress((void**)&bc,  g_c);
    cudaGetSymbolAddress((void**)&bmx, g_mx);
    cudaGetSymbolAddress((void**)&binv, g_inv);

    cudaFuncSetAttribute(hgemm_kernel<0>, cudaFuncAttributeMaxDynamicSharedMemorySize, HG_SMEM);
    cudaFuncSetAttribute(hgemm_kernel<1>, cudaFuncAttributeMaxDynamicSharedMemorySize, HG_SMEM);
    cudaFuncSetAttribute(hsmall_kernel,  cudaFuncAttributeMaxDynamicSharedMemorySize, HS_SMEM);

    dim3 bgrid(4, 256);   // big GEMM grid

    // all 7 weight transposes in one launch
    TransBatch tb;
    tb.src[0]=Wg3;  tb.dst[0]=WgH;
    tb.src[1]=Wesa; tb.dst[1]=WeH;
    tb.src[2]=Wra;  tb.dst[2]=WraT;
    tb.src[3]=Wrb;  tb.dst[3]=WrbT;
    tb.src[4]=Wg1;  tb.dst[4]=Wg1T;
    tb.src[5]=Wg2;  tb.dst[5]=Wg2T;
    tb.src[6]=Wgo;  tb.dst[6]=WgoT;
    transsplit_kernel<<<dim3(16,16,7), dim3(32,8)>>>(tb);

    // x0 -> fp16 ; c = b_rel @ Wg3 + b_gr
    tohalf_kernel<<<XROWS*DD/512, 256>>>(x0, X0H);
    cvec_kernel<<<1, DD>>>(brel, Wg3, bgr, bc);

    // batch1 (A = x0h): u16, v16, s0(f32), t0(f32), x1(f16,tanh)
    HBatch hb1 = {};
    hb1.jobs[0] = { X0H, WraT, nullptr, nullptr, nullptr, UH,  0, 0 };
    hb1.jobs[1] = { X0H, WrbT, nullptr, nullptr, nullptr, VH,  0, 0 };
    hb1.jobs[2] = { X0H, Wg1T, nullptr, nullptr, bs,      nullptr, 0, 0 };
    hb1.jobs[3] = { X0H, Wg2T, nullptr, nullptr, bt,      nullptr, 0, 0 };
    hb1.jobs[4] = { X0H, WgoT, bgo,     nullptr, nullptr, X1H, 1, 0 };
    hsmall_kernel<<<dim3(4,2,5), 256, HS_SMEM>>>(hb1);

    // batch23: s += u@Wg3 ; t += v@Wg3 ; p1 ; q1 ; x2
    HBatch hb23 = {};
    hb23.jobs[0] = { UH,  WgH,  nullptr, bs, bs,      nullptr, 0, 0 };
    hb23.jobs[1] = { VH,  WgH,  nullptr, bt, bt,      nullptr, 0, 0 };
    hb23.jobs[2] = { X1H, Wg1T, nullptr, nullptr, bp, nullptr, 0, 0 };
    hb23.jobs[3] = { X1H, Wg2T, nullptr, nullptr, bq, nullptr, 0, 0 };
    hb23.jobs[4] = { X1H, WgoT, bgo,     nullptr, nullptr, X2H, 1, 0 };
    hsmall_kernel<<<dim3(4,2,5), 256, HS_SMEM>>>(hb23);

    // rel1 = f16(tanh(s_i + t_j + c)) -> plane A
    init_rel_kernel<<<dim3(XROWS, 4), 256>>>(bs, bt, bc, AH);

    // rel2 = tanh(rel1@Wg3 + p1_i + q1_j + b_gr) -> plane B
    hgemm_kernel<0><<<bgrid, 256, HG_SMEM>>>(AH, WgH, bp, bq, bgr, BH);

    // batch4: p2, q2 (f32), x3 (f32, tanh) -> out
    HBatch hb4 = {};
    hb4.jobs[0] = { X2H, Wg1T, nullptr, nullptr, bp,  nullptr, 0, 0 };
    hb4.jobs[1] = { X2H, Wg2T, nullptr, nullptr, bq,  nullptr, 0, 0 };
    hb4.jobs[2] = { X2H, WgoT, bgo,     nullptr, out, nullptr, 1, 0 };
    hsmall_kernel<<<dim3(4,2,3), 256, HS_SMEM>>>(hb4);

    // rel3 = tanh(rel2@Wg3 + p2_i + q2_j + b_gr) -> plane A
    hgemm_kernel<0><<<bgrid, 256, HG_SMEM>>>(BH, WgH, bp, bq, bgr, AH);

    // rel4 = rel3@W_esa + b_esa -> fp16 plane B
    hgemm_kernel<1><<<bgrid, 256, HG_SMEM>>>(AH, WeH, nullptr, nullptr, besa, BH);

    // softmax over i, then weighted sum over j (fp16 rel input, half2 vectorized)
    softmax_stats_kernel<<<XROWS, 256>>>((const __half2*)BH, bmx, binv);
    softmax_out_kernel<<<XROWS, 256>>>((const __half2*)BH, bmx, binv, out + XROWS*DD);
}

// round 15
// speedup vs baseline: 1.0372x; 1.0372x over previous
#include <cuda_runtime.h>
#include <cuda_fp16.h>
#include <math.h>
#include <stdint.h>

#define DD 512
#define NN 128
#define BB 2
#define MBIG (BB*NN*NN)     // 32768 rows for big GEMMs
#define XROWS (BB*NN)       // 256 rows for small GEMMs

// ---------------- scratch (static device allocations; no cudaMalloc) ----------------
__device__ __half g_AH[MBIG*DD];            // rel plane A (fp16)
__device__ __half g_BH[MBIG*DD];            // rel plane B (fp16)
__device__ __half g_WgH[DD*DD];             // Wg3^T  fp16 [n][k]
__device__ __half g_WeH[DD*DD];             // Wesa^T fp16 [n][k]
__device__ __half g_WraT[DD*DD], g_WrbT[DD*DD];
__device__ __half g_Wg1T[DD*DD], g_Wg2T[DD*DD], g_WgoT[DD*DD];
__device__ __half g_X0H[XROWS*DD];
__device__ __half g_UH [XROWS*DD];
__device__ __half g_VH [XROWS*DD];
__device__ __half g_X1H[XROWS*DD];
__device__ __half g_X2H[XROWS*DD];
__device__ float g_s [XROWS*DD];
__device__ float g_t [XROWS*DD];
__device__ float g_p [XROWS*DD];
__device__ float g_q [XROWS*DD];
__device__ float g_c [DD];
__device__ float g_mx [XROWS*DD];
__device__ float g_inv[XROWS*DD];

// ---------------- helpers ----------------
__device__ __forceinline__ uint32_t smem_u32(const void* p) {
    uint32_t a;
    asm("{ .reg .u64 t; cvta.to.shared.u64 t, %1; cvt.u32.u64 %0, t; }" : "=r"(a) : "l"(p));
    return a;
}
__device__ __forceinline__ void mma16816(float* c, const uint32_t* a, const uint32_t* b) {
    asm volatile(
        "mma.sync.aligned.m16n8k16.row.col.f32.f16.f16.f32 "
        "{%0,%1,%2,%3},{%4,%5,%6,%7},{%8,%9},{%0,%1,%2,%3};"
        : "+f"(c[0]), "+f"(c[1]), "+f"(c[2]), "+f"(c[3])
        : "r"(a[0]), "r"(a[1]), "r"(a[2]), "r"(a[3]), "r"(b[0]), "r"(b[1]));
}
#define LDSM4(r0,r1,r2,r3,addr) \
    asm volatile("ldmatrix.sync.aligned.m8n8.x4.shared.b16 {%0,%1,%2,%3}, [%4];" \
        : "=r"(r0),"=r"(r1),"=r"(r2),"=r"(r3) : "r"(addr))
__device__ __forceinline__ void cp16(uint32_t dst, const void* src) {
    asm volatile("cp.async.cg.shared.global [%0], [%1], 16;" :: "r"(dst), "l"(src) : "memory");
}
// fast tanh: abs err ~1e-7, saturates correctly at +/-inf
__device__ __forceinline__ float ftanh(float x) {
    float e = __expf(2.0f * x);
    return 1.0f - __fdividef(2.0f, e + 1.0f);
}

// ---------------- weight transpose+f16 (7 weights) + x0->fp16 in one launch ----------------
struct TransBatch { const float* src[7]; __half* dst[7]; const float* x0; __half* x0h; };
__global__ void transsplit_kernel(TransBatch tb) {
    if (blockIdx.z == 7) {
        // x0 -> fp16: 256 blocks (by*16+bx) x 256 threads x 2 elems = 131072
        int blk = blockIdx.y * 16 + blockIdx.x;
        int tid = threadIdx.y * 32 + threadIdx.x;
        int i = (blk * 256 + tid) * 2;
        float2 v = *(const float2*)(tb.x0 + i);
        *(__half2*)(tb.x0h + i) = __halves2half2(__float2half_rn(v.x), __float2half_rn(v.y));
        return;
    }
    const float* W  = tb.src[blockIdx.z];
    __half*      Wh = tb.dst[blockIdx.z];
    __shared__ float tile[32][33];
    int x = blockIdx.x * 32 + threadIdx.x;
    int y = blockIdx.y * 32 + threadIdx.y;
    #pragma unroll
    for (int r = 0; r < 32; r += 8) tile[threadIdx.y + r][threadIdx.x] = W[(y + r) * DD + x];
    __syncthreads();
    x = blockIdx.y * 32 + threadIdx.x;   // now k index
    y = blockIdx.x * 32 + threadIdx.y;   // now n index
    #pragma unroll
    for (int r = 0; r < 32; r += 8)
        Wh[(y + r) * DD + x] = __float2half_rn(tile[threadIdx.x][threadIdx.y + r]);
}

// ---------------- c = b_rel @ Wg3 + b_gr  (4 blocks x 128 threads) ----------------
__global__ void cvec_kernel(const float* __restrict__ b_rel,
                            const float* __restrict__ Wg3,
                            const float* __restrict__ b_gr,
                            float* __restrict__ c) {
    int d = blockIdx.x * 128 + threadIdx.x;
    float acc = b_gr[d];
    #pragma unroll 8
    for (int k = 0; k < DD; ++k)
        acc += b_rel[k] * Wg3[k*DD + d];
    c[d] = acc;
}

// ---------------- rel1 init: f16(tanh(s_i + t_j + c)) ----------------
__global__ __launch_bounds__(256)
void init_rel_kernel(const float* __restrict__ s, const float* __restrict__ t,
                     const float* __restrict__ c, __half* __restrict__ RH) {
    __shared__ float srow[DD];
    int bi = blockIdx.x;                 // b*128 + i
    int b  = bi >> 7;
    int tid = threadIdx.x;
    #pragma unroll
    for (int d = tid; d < DD; d += 256) srow[d] = s[bi * DD + d] + c[d];
    __syncthreads();
    int j0 = blockIdx.y * 32;
    int d = tid * 2;
    for (int j = j0; j < j0 + 32; ++j) {
        const float* trow = t + (size_t)((b << 7) + j) * DD;
        float v0 = ftanh(srow[d]   + trow[d]);
        float v1 = ftanh(srow[d+1] + trow[d+1]);
        size_t m = (size_t)bi * NN + j;
        *(__half2*)&RH[m * DD + d] = __halves2half2(__float2half_rn(v0), __float2half_rn(v1));
    }
}

#define HG_SMEM (3*20480 + 512)
#define HS_SMEM (5*20480)

// ---------------- small batched tensor GEMM (5-stage ring): C = act?(A@Wt [+bias] [+Cadd]) ----------------
struct HJob {
    const __half* A; const __half* W; const float* bias; const float* Cadd;
    float* Cf; __half* Ch; int act; int pad;
};
struct HBatch { HJob jobs[5]; };

__global__ __launch_bounds__(256, 1)
void hsmall_kernel(HBatch batch) {
    HJob jb = batch.jobs[blockIdx.z];
    extern __shared__ __align__(16) char sm[];
    const uint32_t smBase = smem_u32(sm);
    const int tid = threadIdx.x;
    const int n0 = blockIdx.x << 7, m0 = blockIdx.y << 7;

    const int mat = tid >> 7, tt = tid & 127;
    const __half* plane = mat ? (jb.W + (size_t)(n0 + tt) * DD) : (jb.A + (size_t)(m0 + tt) * DD);
    const uint32_t dstoff = (uint32_t)mat * 10240u + (uint32_t)tt * 80u;

    const int lane = tid & 31, wid = tid >> 5;
    const int g = lane >> 2, q = lane & 3;
    const int wm = (wid & 1) * 64, wn = (wid >> 1) * 32;
    const int lr = lane & 7, sub = lane >> 3;
    const uint32_t rowsel = (uint32_t)((sub & 1) * 8 + lr);
    const uint32_t colsel = (uint32_t)((sub >> 1) * 16);
    const uint32_t aoff = (uint32_t)(wm + rowsel) * 80u + colsel;
    const uint32_t boff = 10240u + (uint32_t)(wn + rowsel) * 80u + colsel;

    float cacc[4][4][4];
    #pragma unroll
    for (int a = 0; a < 4; ++a)
        #pragma unroll
        for (int b = 0; b < 4; ++b)
            #pragma unroll
            for (int e = 0; e < 4; ++e) cacc[a][b][e] = 0.f;

    // prologue: chunks 0..3 -> stages 0..3
    #pragma unroll
    for (int c0 = 0; c0 < 4; ++c0) {
        uint32_t d = smBase + (uint32_t)c0 * 20480u + dstoff;
        const __half* sp = plane + c0 * 32;
        #pragma unroll
        for (int sg = 0; sg < 4; ++sg) cp16(d + sg*16, sp + sg*8);
        asm volatile("cp.async.commit_group;" ::: "memory");
    }

    int stComp = 0;
    for (int kc = 0; kc < 16; ++kc) {
        asm volatile("cp.async.wait_group 3;" ::: "memory");
        __syncthreads();

        if (kc + 4 < 16) {
            int stLoad = stComp - 1; if (stLoad < 0) stLoad = 4;
            uint32_t d = smBase + (uint32_t)stLoad * 20480u + dstoff;
            const __half* sp = plane + (kc + 4) * 32;
            #pragma unroll
            for (int sg = 0; sg < 4; ++sg) cp16(d + sg*16, sp + sg*8);
        }
        asm volatile("cp.async.commit_group;" ::: "memory");

        uint32_t bufb = smBase + (uint32_t)stComp * 20480u;
        #pragma unroll
        for (int ks = 0; ks < 2; ++ks) {
            uint32_t kso = (uint32_t)(ks * 32);
            uint32_t bfh[4][2];
            #pragma unroll
            for (int ntp = 0; ntp < 2; ++ntp) {
                uint32_t ba = bufb + boff + (uint32_t)ntp * 1280u + kso;
                uint32_t r0, r1, r2, r3;
                LDSM4(r0, r1, r2, r3, ba);
                bfh[2*ntp][0]=r0; bfh[2*ntp+1][0]=r1; bfh[2*ntp][1]=r2; bfh[2*ntp+1][1]=r3;
            }
            #pragma unroll
            for (int mt = 0; mt < 4; ++mt) {
                uint32_t aa = bufb + aoff + (uint32_t)mt * 1280u + kso;
                uint32_t ah[4];
                LDSM4(ah[0], ah[1], ah[2], ah[3], aa);
                #pragma unroll
                for (int nt = 0; nt < 4; ++nt)
                    mma16816(cacc[mt][nt], ah, bfh[nt]);
            }
        }
        if (++stComp == 5) stComp = 0;
    }

    // ---- epilogue ----
    #pragma unroll
    for (int mt = 0; mt < 4; ++mt) {
        #pragma unroll
        for (int nt = 0; nt < 4; ++nt) {
            int col = n0 + wn + nt*8 + q*2;
            float b0 = 0.f, b1 = 0.f;
            if (jb.bias) { b0 = jb.bias[col]; b1 = jb.bias[col + 1]; }
            #pragma unroll
            for (int rh = 0; rh < 2; ++rh) {
                int r = m0 + wm + mt*16 + g + rh*8;
                float v0 = cacc[mt][nt][rh*2 + 0] + b0;
                float v1 = cacc[mt][nt][rh*2 + 1] + b1;
                if (jb.Cadd) {
                    float2 cv = *(const float2*)(jb.Cadd + (size_t)r * DD + col);
                    v0 += cv.x; v1 += cv.y;
                }
                if (jb.act) { v0 = ftanh(v0); v1 = ftanh(v1); }
                if (jb.Cf)
                    *(float2*)(jb.Cf + (size_t)r * DD + col) = make_float2(v0, v1);
                else
                    *(__half2*)(jb.Ch + (size_t)r * DD + col) =
                        __halves2half2(__float2half_rn(v0), __float2half_rn(v1));
            }
        }
    }
}

// ================= big GEMM via mma.sync (fp16, 3-stage cp.async ring) =================
// Epilogue P-row + bias cached in smem (P row is constant per CTA: ii = m0>>7).
template<int MODE>
__global__ __launch_bounds__(256, 2)
void hgemm_kernel(const __half* __restrict__ Ah, const __half* __restrict__ Bh,
                  const float* __restrict__ P, const float* __restrict__ Q,
                  const float* __restrict__ bias, __half* __restrict__ Chi) {
    extern __shared__ __align__(16) char sm[];
    const uint32_t smBase = smem_u32(sm);
    float* smPb = (float*)(sm + 3*20480);   // 128 floats: P_row + bias (or bias only)
    const int tid = threadIdx.x;
    const int n0 = blockIdx.x << 7, m0 = blockIdx.y << 7;

    // fill P+bias cache (before first sync of mainloop)
    if (tid < 128) {
        float v = bias[n0 + tid];
        if (MODE == 0) v += P[(size_t)(m0 >> 7) * DD + n0 + tid];
        smPb[tid] = v;
    }

    const int mat = tid >> 7, tt = tid & 127;
    const __half* plane = mat ? (Bh + (size_t)(n0 + tt) * DD) : (Ah + (size_t)(m0 + tt) * DD);
    const uint32_t dstoff = (uint32_t)mat * 10240u + (uint32_t)tt * 80u;

    const int lane = tid & 31, wid = tid >> 5;
    const int g = lane >> 2, q = lane & 3;
    const int wm = (wid & 1) * 64, wn = (wid >> 1) * 32;
    const int lr = lane & 7, sub = lane >> 3;
    const uint32_t rowsel = (uint32_t)((sub & 1) * 8 + lr);
    const uint32_t colsel = (uint32_t)((sub >> 1) * 16);
    const uint32_t aoff = (uint32_t)(wm + rowsel) * 80u + colsel;
    const uint32_t boff = 10240u + (uint32_t)(wn + rowsel) * 80u + colsel;

    const uint32_t stage0 = smBase, stage1 = smBase + 20480u, stage2 = smBase + 40960u;

    float cacc[4][4][4];
    #pragma unroll
    for (int a = 0; a < 4; ++a)
        #pragma unroll
        for (int b = 0; b < 4; ++b)
            #pragma unroll
            for (int e = 0; e < 4; ++e) cacc[a][b][e] = 0.f;

    {
        uint32_t d = stage0 + dstoff;
        #pragma unroll
        for (int sg = 0; sg < 4; ++sg) cp16(d + sg*16, plane + sg*8);
        asm volatile("cp.async.commit_group;" ::: "memory");
        d = stage1 + dstoff;
        const __half* sp = plane + 32;
        #pragma unroll
        for (int sg = 0; sg < 4; ++sg) cp16(d + sg*16, sp + sg*8);
        asm volatile("cp.async.commit_group;" ::: "memory");
    }

    uint32_t stComp = stage0, stLoad = stage2;
    for (int kc = 0; kc < 16; ++kc) {
        if (kc < 15) asm volatile("cp.async.wait_group 1;" ::: "memory");
        else         asm volatile("cp.async.wait_group 0;" ::: "memory");
        __syncthreads();

        if (kc + 2 < 16) {
            uint32_t d = stLoad + dstoff;
            const __half* sp = plane + (kc + 2) * 32;
            #pragma unroll
            for (int sg = 0; sg < 4; ++sg) cp16(d + sg*16, sp + sg*8);
            asm volatile("cp.async.commit_group;" ::: "memory");
        }

        uint32_t bufb = stComp;
        #pragma unroll
        for (int ks = 0; ks < 2; ++ks) {
            uint32_t kso = (uint32_t)(ks * 32);
            uint32_t bfh[4][2];
            #pragma unroll
            for (int ntp = 0; ntp < 2; ++ntp) {
                uint32_t ba = bufb + boff + (uint32_t)ntp * 1280u + kso;
                uint32_t r0, r1, r2, r3;
                LDSM4(r0, r1, r2, r3, ba);
                bfh[2*ntp][0]=r0; bfh[2*ntp+1][0]=r1; bfh[2*ntp][1]=r2; bfh[2*ntp+1][1]=r3;
            }
            #pragma unroll
            for (int mt = 0; mt < 4; ++mt) {
                uint32_t aa = bufb + aoff + (uint32_t)mt * 1280u + kso;
                uint32_t ah[4];
                LDSM4(ah[0], ah[1], ah[2], ah[3], aa);
                #pragma unroll
                for (int nt = 0; nt < 4; ++nt)
                    mma16816(cacc[mt][nt], ah, bfh[nt]);
            }
        }
        uint32_t newComp = (stComp == stage2) ? stage0 : stComp + 20480u;
        stLoad = stComp;
        stComp = newComp;
    }

    // ---- epilogue ----
    #pragma unroll
    for (int mt = 0; mt < 4; ++mt) {
        #pragma unroll
        for (int nt = 0; nt < 4; ++nt) {
            int lcol = wn + nt*8 + q*2;      // 0..127 within tile
            int col  = n0 + lcol;
            float pb0 = smPb[lcol], pb1 = smPb[lcol + 1];
            #pragma unroll
            for (int rh = 0; rh < 2; ++rh) {
                int r = m0 + wm + mt*16 + g + rh*8;
                float v0 = cacc[mt][nt][rh*2 + 0] + pb0;
                float v1 = cacc[mt][nt][rh*2 + 1] + pb1;
                if (MODE == 0) {
                    int b = r >> 14, jj = r & 127;
                    const float* qr = Q + (size_t)(((b<<7)+jj)) * DD;
                    float2 qv = *(const float2*)(qr + col);
                    v0 = ftanh(v0 + qv.x);
                    v1 = ftanh(v1 + qv.y);
                }
                *(__half2*)&Chi[(size_t)r * DD + col] =
                    __halves2half2(__float2half_rn(v0), __float2half_rn(v1));
            }
        }
    }
}

// ---------------- softmax pass A (half2 vectorized) ----------------
__global__ __launch_bounds__(256)
void softmax_stats_kernel(const __half2* __restrict__ rel2,
                          float* __restrict__ mx, float* __restrict__ inv) {
    int bj = blockIdx.x;            // b*NN + j
    int b = bj >> 7, j = bj & 127;
    int d2 = threadIdx.x;
    const __half2* ptr = rel2 + ((size_t)((b << 14) + j) * DD >> 1) + d2;
    const int strd = NN * DD / 2;
    float2 m = make_float2(-1e30f, -1e30f);
    #pragma unroll 8
    for (int i = 0; i < NN; ++i) {
        float2 v = __half22float2(ptr[(size_t)i * strd]);
        m.x = fmaxf(m.x, v.x); m.y = fmaxf(m.y, v.y);
    }
    float2 s = make_float2(0.f, 0.f);
    #pragma unroll 8
    for (int i = 0; i < NN; ++i) {
        float2 v = __half22float2(ptr[(size_t)i * strd]);
        s.x += __expf(v.x - m.x); s.y += __expf(v.y - m.y);
    }
    int o = bj * DD + d2 * 2;
    *(float2*)(mx + o)  = m;
    *(float2*)(inv + o) = make_float2(1.0f / s.x, 1.0f / s.y);
}

// ---------------- softmax pass B (half2 vectorized) ----------------
__global__ __launch_bounds__(256)
void softmax_out_kernel(const __half2* __restrict__ rel2,
                        const float* __restrict__ mx,
                        const float* __restrict__ inv,
                        float* __restrict__ out) {
    int bi = blockIdx.x;            // b*NN + i
    int b = bi >> 7;
    int d2 = threadIdx.x;
    const __half2* ptr = rel2 + ((size_t)bi * NN * DD >> 1) + d2;
    const float2* mxp = (const float2*)(mx  + (size_t)(b << 7) * DD) + d2;
    const float2* ivp = (const float2*)(inv + (size_t)(b << 7) * DD) + d2;
    const int strd = DD / 2;
    float2 acc = make_float2(0.f, 0.f);
    #pragma unroll 8
    for (int j = 0; j < NN; ++j) {
        float2 v  = __half22float2(ptr[(size_t)j * strd]);
        float2 mm = mxp[j * strd];
        float2 iv = ivp[j * strd];
        acc.x += v.x * __expf(v.x - mm.x) * iv.x;
        acc.y += v.y * __expf(v.y - mm.y) * iv.y;
    }
    *(float2*)(out + (size_t)bi * DD + d2 * 2) = acc;
}

// ---------------- host ----------------
extern "C" void kernel_launch(void* const* d_in, const int* in_sizes, int n_in,
                              void* d_out, int out_size) {
    const float* x0   = (const float*)d_in[0];
    const float* Wrel = (const float*)d_in[1];
    const float* brel = (const float*)d_in[2];
    const float* Wgo  = (const float*)d_in[3];
    const float* bgo  = (const float*)d_in[4];
    const float* Wgr  = (const float*)d_in[5];
    const float* bgr  = (const float*)d_in[6];
    const float* Wesa = (const float*)d_in[7];
    const float* besa = (const float*)d_in[8];
    float* out = (float*)d_out;

    const float* Wra = Wrel;                 // W_rel[0:D]
    const float* Wrb = Wrel + DD*DD;         // W_rel[D:2D]
    const float* Wg1 = Wgr;                  // W_gr[0:D]
    const float* Wg2 = Wgr + DD*DD;          // W_gr[D:2D]
    const float* Wg3 = Wgr + 2*DD*DD;        // W_gr[2D:3D]

    float *bs, *bt, *bp, *bq, *bc, *bmx, *binv;
    __half *AH, *BH, *WgH, *WeH, *WraT, *WrbT, *Wg1T, *Wg2T, *WgoT;
    __half *X0H, *UH, *VH, *X1H, *X2H;
    cudaGetSymbolAddress((void**)&AH, g_AH);
    cudaGetSymbolAddress((void**)&BH, g_BH);
    cudaGetSymbolAddress((void**)&WgH, g_WgH);
    cudaGetSymbolAddress((void**)&WeH, g_WeH);
    cudaGetSymbolAddress((void**)&WraT, g_WraT);
    cudaGetSymbolAddress((void**)&WrbT, g_WrbT);
    cudaGetSymbolAddress((void**)&Wg1T, g_Wg1T);
    cudaGetSymbolAddress((void**)&Wg2T, g_Wg2T);
    cudaGetSymbolAddress((void**)&WgoT, g_WgoT);
    cudaGetSymbolAddress((void**)&X0H, g_X0H);
    cudaGetSymbolAddress((void**)&UH,  g_UH);
    cudaGetSymbolAddress((void**)&VH,  g_VH);
    cudaGetSymbolAddress((void**)&X1H, g_X1H);
    cudaGetSymbolAddress((void**)&X2H, g_X2H);
    cudaGetSymbolAddress((void**)&bs,  g_s);
    cudaGetSymbolAddress((void**)&bt,  g_t);
    cudaGetSymbolAddress((void**)&bp,  g_p);
    cudaGetSymbolAddress((void**)&bq,  g_q);
    cudaGetSymbolAddress((void**)&bc,  g_c);
    cudaGetSymbolAddress((void**)&bmx, g_mx);
    cudaGetSymbolAddress((void**)&binv, g_inv);

    cudaFuncSetAttribute(hgemm_kernel<0>, cudaFuncAttributeMaxDynamicSharedMemorySize, HG_SMEM);
    cudaFuncSetAttribute(hgemm_kernel<1>, cudaFuncAttributeMaxDynamicSharedMemorySize, HG_SMEM);
    cudaFuncSetAttribute(hsmall_kernel,  cudaFuncAttributeMaxDynamicSharedMemorySize, HS_SMEM);

    dim3 bgrid(4, 256);   // big GEMM grid

    // 7 weight transposes + x0->fp16 in one launch
    TransBatch tb;
    tb.src[0]=Wg3;  tb.dst[0]=WgH;
    tb.src[1]=Wesa; tb.dst[1]=WeH;
    tb.src[2]=Wra;  tb.dst[2]=WraT;
    tb.src[3]=Wrb;  tb.dst[3]=WrbT;
    tb.src[4]=Wg1;  tb.dst[4]=Wg1T;
    tb.src[5]=Wg2;  tb.dst[5]=Wg2T;
    tb.src[6]=Wgo;  tb.dst[6]=WgoT;
    tb.x0 = x0; tb.x0h = X0H;
    transsplit_kernel<<<dim3(16,16,8), dim3(32,8)>>>(tb);

    // c = b_rel @ Wg3 + b_gr
    cvec_kernel<<<4, 128>>>(brel, Wg3, bgr, bc);

    // batch1 (A = x0h): u16, v16, s0(f32), t0(f32), x1(f16,tanh)
    HBatch hb1 = {};
    hb1.jobs[0] = { X0H, WraT, nullptr, nullptr, nullptr, UH,  0, 0 };
    hb1.jobs[1] = { X0H, WrbT, nullptr, nullptr, nullptr, VH,  0, 0 };
    hb1.jobs[2] = { X0H, Wg1T, nullptr, nullptr, bs,      nullptr, 0, 0 };
    hb1.jobs[3] = { X0H, Wg2T, nullptr, nullptr, bt,      nullptr, 0, 0 };
    hb1.jobs[4] = { X0H, WgoT, bgo,     nullptr, nullptr, X1H, 1, 0 };
    hsmall_kernel<<<dim3(4,2,5), 256, HS_SMEM>>>(hb1);

    // batch23: s += u@Wg3 ; t += v@Wg3 ; p1 ; q1 ; x2
    HBatch hb23 = {};
    hb23.jobs[0] = { UH,  WgH,  nullptr, bs, bs,      nullptr, 0, 0 };
    hb23.jobs[1] = { VH,  WgH,  nullptr, bt, bt,      nullptr, 0, 0 };
    hb23.jobs[2] = { X1H, Wg1T, nullptr, nullptr, bp, nullptr, 0, 0 };
    hb23.jobs[3] = { X1H, Wg2T, nullptr, nullptr, bq, nullptr, 0, 0 };
    hb23.jobs[4] = { X1H, WgoT, bgo,     nullptr, nullptr, X2H, 1, 0 };
    hsmall_kernel<<<dim3(4,2,5), 256, HS_SMEM>>>(hb23);

    // rel1 = f16(tanh(s_i + t_j + c)) -> plane A
    init_rel_kernel<<<dim3(XROWS, 4), 256>>>(bs, bt, bc, AH);

    // rel2 = tanh(rel1@Wg3 + p1_i + q1_j + b_gr) -> plane B
    hgemm_kernel<0><<<bgrid, 256, HG_SMEM>>>(AH, WgH, bp, bq, bgr, BH);

    // batch4: p2, q2 (f32), x3 (f32, tanh) -> out
    HBatch hb4 = {};
    hb4.jobs[0] = { X2H, Wg1T, nullptr, nullptr, bp,  nullptr, 0, 0 };
    hb4.jobs[1] = { X2H, Wg2T, nullptr, nullptr, bq,  nullptr, 0, 0 };
    hb4.jobs[2] = { X2H, WgoT, bgo,     nullptr, out, nullptr, 1, 0 };
    hsmall_kernel<<<dim3(4,2,3), 256, HS_SMEM>>>(hb4);

    // rel3 = tanh(rel2@Wg3 + p2_i + q2_j + b_gr) -> plane A
    hgemm_kernel<0><<<bgrid, 256, HG_SMEM>>>(BH, WgH, bp, bq, bgr, AH);

    // rel4 = rel3@W_esa + b_esa -> fp16 plane B
    hgemm_kernel<1><<<bgrid, 256, HG_SMEM>>>(AH, WeH, nullptr, nullptr, besa, BH);

    // softmax over i, then weighted sum over j (fp16 rel input, half2 vectorized)
    softmax_stats_kernel<<<XROWS, 256>>>((const __half2*)BH, bmx, binv);
    softmax_out_kernel<<<XROWS, 256>>>((const __half2*)BH, bmx, binv, out + XROWS*DD);
}

// round 16
// speedup vs baseline: 1.1296x; 1.0891x over previous
#include <cuda_runtime.h>
#include <cuda_fp16.h>
#include <math.h>
#include <stdint.h>

#define DD 512
#define NN 128
#define BB 2
#define MBIG (BB*NN*NN)     // 32768 rows for big GEMMs
#define XROWS (BB*NN)       // 256 rows for small GEMMs

// ---------------- scratch (static device allocations; no cudaMalloc) ----------------
__device__ __half g_AH[MBIG*DD];            // rel plane A (fp16)
__device__ __half g_BH[MBIG*DD];            // rel plane B (fp16)
__device__ __half g_WgH[DD*DD];             // Wg3^T  fp16 [n][k]
__device__ __half g_WeH[DD*DD];             // Wesa^T fp16 [n][k]
__device__ __half g_WraT[DD*DD], g_WrbT[DD*DD];
__device__ __half g_Wg1T[DD*DD], g_Wg2T[DD*DD], g_WgoT[DD*DD];
__device__ __half g_X0H[XROWS*DD];
__device__ __half g_UH [XROWS*DD];
__device__ __half g_VH [XROWS*DD];
__device__ __half g_X1H[XROWS*DD];
__device__ __half g_X2H[XROWS*DD];
__device__ float g_s [XROWS*DD];
__device__ float g_t [XROWS*DD];
__device__ float g_p [XROWS*DD];
__device__ float g_q [XROWS*DD];
__device__ float g_p2[XROWS*DD];
__device__ float g_q2[XROWS*DD];
__device__ float g_c [DD];
__device__ float g_mx [XROWS*DD];
__device__ float g_inv[XROWS*DD];

// ---------------- helpers ----------------
__device__ __forceinline__ uint32_t smem_u32(const void* p) {
    uint32_t a;
    asm("{ .reg .u64 t; cvta.to.shared.u64 t, %1; cvt.u32.u64 %0, t; }" : "=r"(a) : "l"(p));
    return a;
}
__device__ __forceinline__ void mma16816(float* c, const uint32_t* a, const uint32_t* b) {
    asm volatile(
        "mma.sync.aligned.m16n8k16.row.col.f32.f16.f16.f32 "
        "{%0,%1,%2,%3},{%4,%5,%6,%7},{%8,%9},{%0,%1,%2,%3};"
        : "+f"(c[0]), "+f"(c[1]), "+f"(c[2]), "+f"(c[3])
        : "r"(a[0]), "r"(a[1]), "r"(a[2]), "r"(a[3]), "r"(b[0]), "r"(b[1]));
}
#define LDSM4(r0,r1,r2,r3,addr) \
    asm volatile("ldmatrix.sync.aligned.m8n8.x4.shared.b16 {%0,%1,%2,%3}, [%4];" \
        : "=r"(r0),"=r"(r1),"=r"(r2),"=r"(r3) : "r"(addr))
__device__ __forceinline__ void cp16(uint32_t dst, const void* src) {
    asm volatile("cp.async.cg.shared.global [%0], [%1], 16;" :: "r"(dst), "l"(src) : "memory");
}
// fast tanh: abs err ~1e-7, saturates correctly at +/-inf
__device__ __forceinline__ float ftanh(float x) {
    float e = __expf(2.0f * x);
    return 1.0f - __fdividef(2.0f, e + 1.0f);
}

// ---------------- weight transpose+f16 (7 weights) + x0->fp16 in one launch ----------------
struct TransBatch { const float* src[7]; __half* dst[7]; const float* x0; __half* x0h; };
__global__ void transsplit_kernel(TransBatch tb) {
    if (blockIdx.z == 7) {
        int blk = blockIdx.y * 16 + blockIdx.x;
        int tid = threadIdx.y * 32 + threadIdx.x;
        int i = (blk * 256 + tid) * 2;
        float2 v = *(const float2*)(tb.x0 + i);
        *(__half2*)(tb.x0h + i) = __halves2half2(__float2half_rn(v.x), __float2half_rn(v.y));
        return;
    }
    const float* W  = tb.src[blockIdx.z];
    __half*      Wh = tb.dst[blockIdx.z];
    __shared__ float tile[32][33];
    int x = blockIdx.x * 32 + threadIdx.x;
    int y = blockIdx.y * 32 + threadIdx.y;
    #pragma unroll
    for (int r = 0; r < 32; r += 8) tile[threadIdx.y + r][threadIdx.x] = W[(y + r) * DD + x];
    __syncthreads();
    x = blockIdx.y * 32 + threadIdx.x;   // now k index
    y = blockIdx.x * 32 + threadIdx.y;   // now n index
    #pragma unroll
    for (int r = 0; r < 32; r += 8)
        Wh[(y + r) * DD + x] = __float2half_rn(tile[threadIdx.x][threadIdx.y + r]);
}

// ---------------- c = b_rel @ Wg3 + b_gr  (4 blocks x 128 threads) ----------------
__global__ void cvec_kernel(const float* __restrict__ b_rel,
                            const float* __restrict__ Wg3,
                            const float* __restrict__ b_gr,
                            float* __restrict__ c) {
    int d = blockIdx.x * 128 + threadIdx.x;
    float acc = b_gr[d];
    #pragma unroll 8
    for (int k = 0; k < DD; ++k)
        acc += b_rel[k] * Wg3[k*DD + d];
    c[d] = acc;
}

// ---------------- rel1 init: f16(tanh(s_i + t_j + c)) ----------------
__global__ __launch_bounds__(256)
void init_rel_kernel(const float* __restrict__ s, const float* __restrict__ t,
                     const float* __restrict__ c, __half* __restrict__ RH) {
    __shared__ float srow[DD];
    int bi = blockIdx.x;                 // b*128 + i
    int b  = bi >> 7;
    int tid = threadIdx.x;
    #pragma unroll
    for (int d = tid; d < DD; d += 256) srow[d] = s[bi * DD + d] + c[d];
    __syncthreads();
    int j0 = blockIdx.y * 32;
    int d = tid * 2;
    for (int j = j0; j < j0 + 32; ++j) {
        const float* trow = t + (size_t)((b << 7) + j) * DD;
        float v0 = ftanh(srow[d]   + trow[d]);
        float v1 = ftanh(srow[d+1] + trow[d+1]);
        size_t m = (size_t)bi * NN + j;
        *(__half2*)&RH[m * DD + d] = __halves2half2(__float2half_rn(v0), __float2half_rn(v1));
    }
}

#define HG_SMEM (3*20480 + 512)
#define HS_SMEM (5*20480)

// ---------------- small batched tensor GEMM (5-stage ring): C = act?(A@Wt [+bias] [+Cadd]) ----------------
struct HJob {
    const __half* A; const __half* W; const float* bias; const float* Cadd;
    float* Cf; __half* Ch; int act; int pad;
};
struct HBatch { HJob jobs[5]; };

__global__ __launch_bounds__(256, 1)
void hsmall_kernel(HBatch batch) {
    HJob jb = batch.jobs[blockIdx.z];
    extern __shared__ __align__(16) char sm[];
    const uint32_t smBase = smem_u32(sm);
    const int tid = threadIdx.x;
    const int n0 = blockIdx.x << 7, m0 = blockIdx.y << 7;

    const int mat = tid >> 7, tt = tid & 127;
    const __half* plane = mat ? (jb.W + (size_t)(n0 + tt) * DD) : (jb.A + (size_t)(m0 + tt) * DD);
    const uint32_t dstoff = (uint32_t)mat * 10240u + (uint32_t)tt * 80u;

    const int lane = tid & 31, wid = tid >> 5;
    const int g = lane >> 2, q = lane & 3;
    const int wm = (wid & 1) * 64, wn = (wid >> 1) * 32;
    const int lr = lane & 7, sub = lane >> 3;
    const uint32_t rowsel = (uint32_t)((sub & 1) * 8 + lr);
    const uint32_t colsel = (uint32_t)((sub >> 1) * 16);
    const uint32_t aoff = (uint32_t)(wm + rowsel) * 80u + colsel;
    const uint32_t boff = 10240u + (uint32_t)(wn + rowsel) * 80u + colsel;

    float cacc[4][4][4];
    #pragma unroll
    for (int a = 0; a < 4; ++a)
        #pragma unroll
        for (int b = 0; b < 4; ++b)
            #pragma unroll
            for (int e = 0; e < 4; ++e) cacc[a][b][e] = 0.f;

    // prologue: chunks 0..3 -> stages 0..3
    #pragma unroll
    for (int c0 = 0; c0 < 4; ++c0) {
        uint32_t d = smBase + (uint32_t)c0 * 20480u + dstoff;
        const __half* sp = plane + c0 * 32;
        #pragma unroll
        for (int sg = 0; sg < 4; ++sg) cp16(d + sg*16, sp + sg*8);
        asm volatile("cp.async.commit_group;" ::: "memory");
    }

    int stComp = 0;
    for (int kc = 0; kc < 16; ++kc) {
        asm volatile("cp.async.wait_group 3;" ::: "memory");
        __syncthreads();

        if (kc + 4 < 16) {
            int stLoad = stComp - 1; if (stLoad < 0) stLoad = 4;
            uint32_t d = smBase + (uint32_t)stLoad * 20480u + dstoff;
            const __half* sp = plane + (kc + 4) * 32;
            #pragma unroll
            for (int sg = 0; sg < 4; ++sg) cp16(d + sg*16, sp + sg*8);
        }
        asm volatile("cp.async.commit_group;" ::: "memory");

        uint32_t bufb = smBase + (uint32_t)stComp * 20480u;
        #pragma unroll
        for (int ks = 0; ks < 2; ++ks) {
            uint32_t kso = (uint32_t)(ks * 32);
            uint32_t bfh[4][2];
            #pragma unroll
            for (int ntp = 0; ntp < 2; ++ntp) {
                uint32_t ba = bufb + boff + (uint32_t)ntp * 1280u + kso;
                uint32_t r0, r1, r2, r3;
                LDSM4(r0, r1, r2, r3, ba);
                bfh[2*ntp][0]=r0; bfh[2*ntp+1][0]=r1; bfh[2*ntp][1]=r2; bfh[2*ntp+1][1]=r3;
            }
            #pragma unroll
            for (int mt = 0; mt < 4; ++mt) {
                uint32_t aa = bufb + aoff + (uint32_t)mt * 1280u + kso;
                uint32_t ah[4];
                LDSM4(ah[0], ah[1], ah[2], ah[3], aa);
                #pragma unroll
                for (int nt = 0; nt < 4; ++nt)
                    mma16816(cacc[mt][nt], ah, bfh[nt]);
            }
        }
        if (++stComp == 5) stComp = 0;
    }

    // ---- epilogue ----
    #pragma unroll
    for (int mt = 0; mt < 4; ++mt) {
        #pragma unroll
        for (int nt = 0; nt < 4; ++nt) {
            int col = n0 + wn + nt*8 + q*2;
            float b0 = 0.f, b1 = 0.f;
            if (jb.bias) { b0 = jb.bias[col]; b1 = jb.bias[col + 1]; }
            #pragma unroll
            for (int rh = 0; rh < 2; ++rh) {
                int r = m0 + wm + mt*16 + g + rh*8;
                float v0 = cacc[mt][nt][rh*2 + 0] + b0;
                float v1 = cacc[mt][nt][rh*2 + 1] + b1;
                if (jb.Cadd) {
                    float2 cv = *(const float2*)(jb.Cadd + (size_t)r * DD + col);
                    v0 += cv.x; v1 += cv.y;
                }
                if (jb.act) { v0 = ftanh(v0); v1 = ftanh(v1); }
                if (jb.Cf)
                    *(float2*)(jb.Cf + (size_t)r * DD + col) = make_float2(v0, v1);
                else
                    *(__half2*)(jb.Ch + (size_t)r * DD + col) =
                        __halves2half2(__float2half_rn(v0), __float2half_rn(v1));
            }
        }
    }
}

// ================= big GEMM via mma.sync (fp16, 3-stage cp.async ring) =================
// Epilogue P-row + bias cached in smem (P row is constant per CTA: ii = m0>>7).
template<int MODE>
__global__ __launch_bounds__(256, 2)
void hgemm_kernel(const __half* __restrict__ Ah, const __half* __restrict__ Bh,
                  const float* __restrict__ P, const float* __restrict__ Q,
                  const float* __restrict__ bias, __half* __restrict__ Chi) {
    extern __shared__ __align__(16) char sm[];
    const uint32_t smBase = smem_u32(sm);
    float* smPb = (float*)(sm + 3*20480);   // 128 floats: P_row + bias (or bias only)
    const int tid = threadIdx.x;
    const int n0 = blockIdx.x << 7, m0 = blockIdx.y << 7;

    if (tid < 128) {
        float v = bias[n0 + tid];
        if (MODE == 0) v += P[(size_t)(m0 >> 7) * DD + n0 + tid];
        smPb[tid] = v;
    }

    const int mat = tid >> 7, tt = tid & 127;
    const __half* plane = mat ? (Bh + (size_t)(n0 + tt) * DD) : (Ah + (size_t)(m0 + tt) * DD);
    const uint32_t dstoff = (uint32_t)mat * 10240u + (uint32_t)tt * 80u;

    const int lane = tid & 31, wid = tid >> 5;
    const int g = lane >> 2, q = lane & 3;
    const int wm = (wid & 1) * 64, wn = (wid >> 1) * 32;
    const int lr = lane & 7, sub = lane >> 3;
    const uint32_t rowsel = (uint32_t)((sub & 1) * 8 + lr);
    const uint32_t colsel = (uint32_t)((sub >> 1) * 16);
    const uint32_t aoff = (uint32_t)(wm + rowsel) * 80u + colsel;
    const uint32_t boff = 10240u + (uint32_t)(wn + rowsel) * 80u + colsel;

    const uint32_t stage0 = smBase, stage1 = smBase + 20480u, stage2 = smBase + 40960u;

    float cacc[4][4][4];
    #pragma unroll
    for (int a = 0; a < 4; ++a)
        #pragma unroll
        for (int b = 0; b < 4; ++b)
            #pragma unroll
            for (int e = 0; e < 4; ++e) cacc[a][b][e] = 0.f;

    {
        uint32_t d = stage0 + dstoff;
        #pragma unroll
        for (int sg = 0; sg < 4; ++sg) cp16(d + sg*16, plane + sg*8);
        asm volatile("cp.async.commit_group;" ::: "memory");
        d = stage1 + dstoff;
        const __half* sp = plane + 32;
        #pragma unroll
        for (int sg = 0; sg < 4; ++sg) cp16(d + sg*16, sp + sg*8);
        asm volatile("cp.async.commit_group;" ::: "memory");
    }

    uint32_t stComp = stage0, stLoad = stage2;
    for (int kc = 0; kc < 16; ++kc) {
        if (kc < 15) asm volatile("cp.async.wait_group 1;" ::: "memory");
        else         asm volatile("cp.async.wait_group 0;" ::: "memory");
        __syncthreads();

        if (kc + 2 < 16) {
            uint32_t d = stLoad + dstoff;
            const __half* sp = plane + (kc + 2) * 32;
            #pragma unroll
            for (int sg = 0; sg < 4; ++sg) cp16(d + sg*16, sp + sg*8);
            asm volatile("cp.async.commit_group;" ::: "memory");
        }

        uint32_t bufb = stComp;
        #pragma unroll
        for (int ks = 0; ks < 2; ++ks) {
            uint32_t kso = (uint32_t)(ks * 32);
            uint32_t bfh[4][2];
            #pragma unroll
            for (int ntp = 0; ntp < 2; ++ntp) {
                uint32_t ba = bufb + boff + (uint32_t)ntp * 1280u + kso;
                uint32_t r0, r1, r2, r3;
                LDSM4(r0, r1, r2, r3, ba);
                bfh[2*ntp][0]=r0; bfh[2*ntp+1][0]=r1; bfh[2*ntp][1]=r2; bfh[2*ntp+1][1]=r3;
            }
            #pragma unroll
            for (int mt = 0; mt < 4; ++mt) {
                uint32_t aa = bufb + aoff + (uint32_t)mt * 1280u + kso;
                uint32_t ah[4];
                LDSM4(ah[0], ah[1], ah[2], ah[3], aa);
                #pragma unroll
                for (int nt = 0; nt < 4; ++nt)
                    mma16816(cacc[mt][nt], ah, bfh[nt]);
            }
        }
        uint32_t newComp = (stComp == stage2) ? stage0 : stComp + 20480u;
        stLoad = stComp;
        stComp = newComp;
    }

    // ---- epilogue ----
    #pragma unroll
    for (int mt = 0; mt < 4; ++mt) {
        #pragma unroll
        for (int nt = 0; nt < 4; ++nt) {
            int lcol = wn + nt*8 + q*2;      // 0..127 within tile
            int col  = n0 + lcol;
            float pb0 = smPb[lcol], pb1 = smPb[lcol + 1];
            #pragma unroll
            for (int rh = 0; rh < 2; ++rh) {
                int r = m0 + wm + mt*16 + g + rh*8;
                float v0 = cacc[mt][nt][rh*2 + 0] + pb0;
                float v1 = cacc[mt][nt][rh*2 + 1] + pb1;
                if (MODE == 0) {
                    int b = r >> 14, jj = r & 127;
                    const float* qr = Q + (size_t)(((b<<7)+jj)) * DD;
                    float2 qv = *(const float2*)(qr + col);
                    v0 = ftanh(v0 + qv.x);
                    v1 = ftanh(v1 + qv.y);
                }
                *(__half2*)&Chi[(size_t)r * DD + col] =
                    __halves2half2(__float2half_rn(v0), __float2half_rn(v1));
            }
        }
    }
}

// ---------------- softmax pass A (half2 vectorized) ----------------
__global__ __launch_bounds__(256)
void softmax_stats_kernel(const __half2* __restrict__ rel2,
                          float* __restrict__ mx, float* __restrict__ inv) {
    int bj = blockIdx.x;            // b*NN + j
    int b = bj >> 7, j = bj & 127;
    int d2 = threadIdx.x;
    const __half2* ptr = rel2 + ((size_t)((b << 14) + j) * DD >> 1) + d2;
    const int strd = NN * DD / 2;
    float2 m = make_float2(-1e30f, -1e30f);
    #pragma unroll 8
    for (int i = 0; i < NN; ++i) {
        float2 v = __half22float2(ptr[(size_t)i * strd]);
        m.x = fmaxf(m.x, v.x); m.y = fmaxf(m.y, v.y);
    }
    float2 s = make_float2(0.f, 0.f);
    #pragma unroll 8
    for (int i = 0; i < NN; ++i) {
        float2 v = __half22float2(ptr[(size_t)i * strd]);
        s.x += __expf(v.x - m.x); s.y += __expf(v.y - m.y);
    }
    int o = bj * DD + d2 * 2;
    *(float2*)(mx + o)  = m;
    *(float2*)(inv + o) = make_float2(1.0f / s.x, 1.0f / s.y);
}

// ---------------- softmax pass B (half2 vectorized) ----------------
__global__ __launch_bounds__(256)
void softmax_out_kernel(const __half2* __restrict__ rel2,
                        const float* __restrict__ mx,
                        const float* __restrict__ inv,
                        float* __restrict__ out) {
    int bi = blockIdx.x;            // b*NN + i
    int b = bi >> 7;
    int d2 = threadIdx.x;
    const __half2* ptr = rel2 + ((size_t)bi * NN * DD >> 1) + d2;
    const float2* mxp = (const float2*)(mx  + (size_t)(b << 7) * DD) + d2;
    const float2* ivp = (const float2*)(inv + (size_t)(b << 7) * DD) + d2;
    const int strd = DD / 2;
    float2 acc = make_float2(0.f, 0.f);
    #pragma unroll 8
    for (int j = 0; j < NN; ++j) {
        float2 v  = __half22float2(ptr[(size_t)j * strd]);
        float2 mm = mxp[j * strd];
        float2 iv = ivp[j * strd];
        acc.x += v.x * __expf(v.x - mm.x) * iv.x;
        acc.y += v.y * __expf(v.y - mm.y) * iv.y;
    }
    *(float2*)(out + (size_t)bi * DD + d2 * 2) = acc;
}

// ---------------- host ----------------
extern "C" void kernel_launch(void* const* d_in, const int* in_sizes, int n_in,
                              void* d_out, int out_size) {
    const float* x0   = (const float*)d_in[0];
    const float* Wrel = (const float*)d_in[1];
    const float* brel = (const float*)d_in[2];
    const float* Wgo  = (const float*)d_in[3];
    const float* bgo  = (const float*)d_in[4];
    const float* Wgr  = (const float*)d_in[5];
    const float* bgr  = (const float*)d_in[6];
    const float* Wesa = (const float*)d_in[7];
    const float* besa = (const float*)d_in[8];
    float* out = (float*)d_out;

    const float* Wra = Wrel;                 // W_rel[0:D]
    const float* Wrb = Wrel + DD*DD;         // W_rel[D:2D]
    const float* Wg1 = Wgr;                  // W_gr[0:D]
    const float* Wg2 = Wgr + DD*DD;          // W_gr[D:2D]
    const float* Wg3 = Wgr + 2*DD*DD;        // W_gr[2D:3D]

    float *bs, *bt, *bp, *bq, *bp2, *bq2, *bc, *bmx, *binv;
    __half *AH, *BH, *WgH, *WeH, *WraT, *WrbT, *Wg1T, *Wg2T, *WgoT;
    __half *X0H, *UH, *VH, *X1H, *X2H;
    cudaGetSymbolAddress((void**)&AH, g_AH);
    cudaGetSymbolAddress((void**)&BH, g_BH);
    cudaGetSymbolAddress((void**)&WgH, g_WgH);
    cudaGetSymbolAddress((void**)&WeH, g_WeH);
    cudaGetSymbolAddress((void**)&WraT, g_WraT);
    cudaGetSymbolAddress((void**)&WrbT, g_WrbT);
    cudaGetSymbolAddress((void**)&Wg1T, g_Wg1T);
    cudaGetSymbolAddress((void**)&Wg2T, g_Wg2T);
    cudaGetSymbolAddress((void**)&WgoT, g_WgoT);
    cudaGetSymbolAddress((void**)&X0H, g_X0H);
    cudaGetSymbolAddress((void**)&UH,  g_UH);
    cudaGetSymbolAddress((void**)&VH,  g_VH);
    cudaGetSymbolAddress((void**)&X1H, g_X1H);
    cudaGetSymbolAddress((void**)&X2H, g_X2H);
    cudaGetSymbolAddress((void**)&bs,  g_s);
    cudaGetSymbolAddress((void**)&bt,  g_t);
    cudaGetSymbolAddress((void**)&bp,  g_p);
    cudaGetSymbolAddress((void**)&bq,  g_q);
    cudaGetSymbolAddress((void**)&bp2, g_p2);
    cudaGetSymbolAddress((void**)&bq2, g_q2);
    cudaGetSymbolAddress((void**)&bc,  g_c);
    cudaGetSymbolAddress((void**)&bmx, g_mx);
    cudaGetSymbolAddress((void**)&binv, g_inv);

    cudaFuncSetAttribute(hgemm_kernel<0>, cudaFuncAttributeMaxDynamicSharedMemorySize, HG_SMEM);
    cudaFuncSetAttribute(hgemm_kernel<1>, cudaFuncAttributeMaxDynamicSharedMemorySize, HG_SMEM);
    cudaFuncSetAttribute(hsmall_kernel,  cudaFuncAttributeMaxDynamicSharedMemorySize, HS_SMEM);

    // side stream + events for DAG parallelism (graph fork/join pattern)
    cudaStream_t s2;
    cudaStreamCreateWithFlags(&s2, cudaStreamNonBlocking);
    cudaEvent_t evTop, evCvec, evFork, evJoin;
    cudaEventCreateWithFlags(&evTop,  cudaEventDisableTiming);
    cudaEventCreateWithFlags(&evCvec, cudaEventDisableTiming);
    cudaEventCreateWithFlags(&evFork, cudaEventDisableTiming);
    cudaEventCreateWithFlags(&evJoin, cudaEventDisableTiming);

    dim3 bgrid(4, 256);   // big GEMM grid

    // fork: cvec on side stream (depends only on raw inputs)
    cudaEventRecord(evTop, 0);
    cudaStreamWaitEvent(s2, evTop, 0);
    cvec_kernel<<<4, 128, 0, s2>>>(brel, Wg3, bgr, bc);
    cudaEventRecord(evCvec, s2);

    // main stream: 7 weight transposes + x0->fp16 in one launch
    TransBatch tb;
    tb.src[0]=Wg3;  tb.dst[0]=WgH;
    tb.src[1]=Wesa; tb.dst[1]=WeH;
    tb.src[2]=Wra;  tb.dst[2]=WraT;
    tb.src[3]=Wrb;  tb.dst[3]=WrbT;
    tb.src[4]=Wg1;  tb.dst[4]=Wg1T;
    tb.src[5]=Wg2;  tb.dst[5]=Wg2T;
    tb.src[6]=Wgo;  tb.dst[6]=WgoT;
    tb.x0 = x0; tb.x0h = X0H;
    transsplit_kernel<<<dim3(16,16,8), dim3(32,8)>>>(tb);

    // batch1 (A = x0h): u16, v16, s0(f32), t0(f32), x1(f16,tanh)
    HBatch hb1 = {};
    hb1.jobs[0] = { X0H, WraT, nullptr, nullptr, nullptr, UH,  0, 0 };
    hb1.jobs[1] = { X0H, WrbT, nullptr, nullptr, nullptr, VH,  0, 0 };
    hb1.jobs[2] = { X0H, Wg1T, nullptr, nullptr, bs,      nullptr, 0, 0 };
    hb1.jobs[3] = { X0H, Wg2T, nullptr, nullptr, bt,      nullptr, 0, 0 };
    hb1.jobs[4] = { X0H, WgoT, bgo,     nullptr, nullptr, X1H, 1, 0 };
    hsmall_kernel<<<dim3(4,2,5), 256, HS_SMEM>>>(hb1);

    // batch23: s += u@Wg3 ; t += v@Wg3 ; p1 ; q1 ; x2
    HBatch hb23 = {};
    hb23.jobs[0] = { UH,  WgH,  nullptr, bs, bs,      nullptr, 0, 0 };
    hb23.jobs[1] = { VH,  WgH,  nullptr, bt, bt,      nullptr, 0, 0 };
    hb23.jobs[2] = { X1H, Wg1T, nullptr, nullptr, bp, nullptr, 0, 0 };
    hb23.jobs[3] = { X1H, Wg2T, nullptr, nullptr, bq, nullptr, 0, 0 };
    hb23.jobs[4] = { X1H, WgoT, bgo,     nullptr, nullptr, X2H, 1, 0 };
    hsmall_kernel<<<dim3(4,2,5), 256, HS_SMEM>>>(hb23);

    // fork after batch23: batch4 on side stream (needs X2H only; writes bp2/bq2/out)
    cudaEventRecord(evFork, 0);
    cudaStreamWaitEvent(s2, evFork, 0);
    HBatch hb4 = {};
    hb4.jobs[0] = { X2H, Wg1T, nullptr, nullptr, bp2, nullptr, 0, 0 };  // p2
    hb4.jobs[1] = { X2H, Wg2T, nullptr, nullptr, bq2, nullptr, 0, 0 };  // q2
    hb4.jobs[2] = { X2H, WgoT, bgo,     nullptr, out, nullptr, 1, 0 };  // x3 -> out
    hsmall_kernel<<<dim3(4,2,3), 256, HS_SMEM, s2>>>(hb4);
    cudaEventRecord(evJoin, s2);

    // main stream: rel1 init (needs bc from cvec) + layer-1 big GEMM (uses bp/bq)
    cudaStreamWaitEvent(0, evCvec, 0);
    init_rel_kernel<<<dim3(XROWS, 4), 256>>>(bs, bt, bc, AH);
    hgemm_kernel<0><<<bgrid, 256, HG_SMEM>>>(AH, WgH, bp, bq, bgr, BH);

    // join: hgemm#2 needs bp2/bq2 from batch4
    cudaStreamWaitEvent(0, evJoin, 0);
    hgemm_kernel<0><<<bgrid, 256, HG_SMEM>>>(BH, WgH, bp2, bq2, bgr, AH);

    // rel4 = rel3@W_esa + b_esa -> fp16 plane B
    hgemm_kernel<1><<<bgrid, 256, HG_SMEM>>>(AH, WeH, nullptr, nullptr, besa, BH);

    // softmax over i, then weighted sum over j (fp16 rel input, half2 vectorized)
    softmax_stats_kernel<<<XROWS, 256>>>((const __half2*)BH, bmx, binv);
    softmax_out_kernel<<<XROWS, 256>>>((const __half2*)BH, bmx, binv, out + XROWS*DD);

    cudaEventDestroy(evTop);
    cudaEventDestroy(evCvec);
    cudaEventDestroy(evFork);
    cudaEventDestroy(evJoin);
    cudaStreamDestroy(s2);
}